// round 13
// baseline (speedup 1.0000x reference)
#include <cuda_runtime.h>
#include <cuda_bf16.h>

// Problem constants: input shape (N=4, C=3, 128,128,128), fp32.
#define S_SPATIAL   (128 * 128 * 128)          // 2,097,152 contiguous elems per (n,c) segment
#define N_BATCH     4
#define C_CHAN      3
#define M_PER_CH    ((long long)N_BATCH * S_SPATIAL)   // 8,388,608 elems per channel

#define THREADS     512
#define BLK_PER_CH  148                         // one block per SM per channel
#define TOTAL_BLOCKS (C_CHAN * BLK_PER_CH)      // 444 = 3 blocks/SM exactly (single wave)

#define CHUNK_ELEMS 8192                        // channel-uniform chunk
#define CHUNK_VEC4  (CHUNK_ELEMS / 4)           // 2048 vec4 = 4 per thread
#define CH_PER_SEG  (S_SPATIAL / CHUNK_ELEMS)   // 256 chunks per (n,c) segment
#define CPC         (N_BATCH * CH_PER_SEG)      // 1024 chunks per channel

// Per-block partials: block (ch, t) writes slot [ch][t]; every slot rewritten
// every launch -> no init kernel needed, deterministic graph replays.
__device__ float    g_psum[C_CHAN][BLK_PER_CH];
__device__ int      g_pcnt[C_CHAN][BLK_PER_CH];
// Arrival counter; last block resets it to 0 each launch.
__device__ unsigned g_arrive = 0u;

__global__ __launch_bounds__(THREADS, 3) void bce_fused_kernel(
    const float* __restrict__ p_in,
    const float* __restrict__ t_in,
    float* __restrict__ out)
{
    const int b   = blockIdx.x;
    const int ch  = b % C_CHAN;                 // channel, uniform per block
    const int t   = b / C_CHAN;                 // block index within channel (0..147)
    const int tid = threadIdx.x;

    float sum = 0.0f;
    int   cnt = 0;

    // Grid-stride over this channel's 1024 chunks (6 or 7 chunks per block).
    for (int j = t; j < CPC; j += BLK_PER_CH) {
        const int n   = j >> 8;                 // batch index (256 chunks/segment)
        const int pos = j & 255;                // chunk within segment
        const size_t base = (size_t)(n * C_CHAN + ch) * S_SPATIAL
                          + (size_t)pos * CHUNK_ELEMS;
        const float4* __restrict__ p4 = (const float4*)(p_in + base);
        const float4* __restrict__ t4 = (const float4*)(t_in + base);

        // Round-8 mainloop body: 4 fully-unrolled vec4 iterations per thread.
        #pragma unroll 4
        for (int i = tid; i < CHUNK_VEC4; i += THREADS) {
            float4 pv = p4[i];
            float4 tv = t4[i];
            {
                bool one = (tv.x != 0.0f);
                float x = one ? pv.x : (1.0f - pv.x);
                sum += fmaxf(__logf(x), -100.0f);
                cnt += one;
            }
            {
                bool one = (tv.y != 0.0f);
                float x = one ? pv.y : (1.0f - pv.y);
                sum += fmaxf(__logf(x), -100.0f);
                cnt += one;
            }
            {
                bool one = (tv.z != 0.0f);
                float x = one ? pv.z : (1.0f - pv.z);
                sum += fmaxf(__logf(x), -100.0f);
                cnt += one;
            }
            {
                bool one = (tv.w != 0.0f);
                float x = one ? pv.w : (1.0f - pv.w);
                sum += fmaxf(__logf(x), -100.0f);
                cnt += one;
            }
        }
    }

    // ---- Warp + block reduction ----
    #pragma unroll
    for (int off = 16; off > 0; off >>= 1) {
        sum += __shfl_xor_sync(0xFFFFFFFFu, sum, off);
        cnt += __shfl_xor_sync(0xFFFFFFFFu, cnt, off);
    }

    __shared__ float s_sum[THREADS / 32];
    __shared__ int   s_cnt[THREADS / 32];
    __shared__ bool  s_last;
    const int wid = tid >> 5;
    const int lid = tid & 31;
    if (lid == 0) {
        s_sum[wid] = sum;
        s_cnt[wid] = cnt;
    }
    __syncthreads();

    if (tid == 0) {
        float bsum = 0.0f;
        int   bcnt = 0;
        #pragma unroll
        for (int w = 0; w < THREADS / 32; w++) {
            bsum += s_sum[w];
            bcnt += s_cnt[w];
        }
        g_psum[ch][t] = bsum;
        g_pcnt[ch][t] = bcnt;
        __threadfence();                        // publish partials device-wide
        unsigned prev = atomicAdd(&g_arrive, 1u);
        s_last = (prev == TOTAL_BLOCKS - 1);
    }
    __syncthreads();

    if (!s_last) return;

    // ---- Last block: fp32/int tail over 3 x 148 partials ----
    float fs0 = 0.f, fs1 = 0.f, fs2 = 0.f;
    int   ic0 = 0,   ic1 = 0,   ic2 = 0;
    if (tid < BLK_PER_CH) {
        fs0 = g_psum[0][tid]; ic0 = g_pcnt[0][tid];
        fs1 = g_psum[1][tid]; ic1 = g_pcnt[1][tid];
        fs2 = g_psum[2][tid]; ic2 = g_pcnt[2][tid];
    }

    #pragma unroll
    for (int off = 16; off > 0; off >>= 1) {
        fs0 += __shfl_xor_sync(0xFFFFFFFFu, fs0, off);
        fs1 += __shfl_xor_sync(0xFFFFFFFFu, fs1, off);
        fs2 += __shfl_xor_sync(0xFFFFFFFFu, fs2, off);
        ic0 += __shfl_xor_sync(0xFFFFFFFFu, ic0, off);
        ic1 += __shfl_xor_sync(0xFFFFFFFFu, ic1, off);
        ic2 += __shfl_xor_sync(0xFFFFFFFFu, ic2, off);
    }

    __shared__ float f_sum[C_CHAN][THREADS / 32];
    __shared__ int   f_cnt[C_CHAN][THREADS / 32];
    if (lid == 0) {
        f_sum[0][wid] = fs0; f_sum[1][wid] = fs1; f_sum[2][wid] = fs2;
        f_cnt[0][wid] = ic0; f_cnt[1][wid] = ic1; f_cnt[2][wid] = ic2;
    }
    __syncthreads();

    if (tid == 0) {
        double total = 0.0;
        #pragma unroll
        for (int c = 0; c < C_CHAN; c++) {
            float s = 0.0f;
            int   ones = 0;
            #pragma unroll
            for (int w = 0; w < THREADS / 32; w++) {
                s    += f_sum[c][w];
                ones += f_cnt[c][w];
            }
            double bce = -(double)s / (double)M_PER_CH;        // channel mean, negated
            double wgt = (ones > 0) ? ((double)M_PER_CH / (double)ones)
                                    : 1000.0;                  // EMPTY_WEIGHT
            total += wgt * bce;
        }
        out[0] = (float)(total / (double)C_CHAN);
        g_arrive = 0u;                                         // self-reset for next replay
    }
}

extern "C" void kernel_launch(void* const* d_in, const int* in_sizes, int n_in,
                              void* d_out, int out_size) {
    const float* input  = (const float*)d_in[0];
    const float* target = (const float*)d_in[1];
    float* out = (float*)d_out;

    bce_fused_kernel<<<TOTAL_BLOCKS, THREADS>>>(input, target, out);
}